// round 13
// baseline (speedup 1.0000x reference)
#include <cuda_runtime.h>
#include <cuda_bf16.h>

#define BMAX 32
#define NMAX 640
#define GMAX 512        // max frame-groups per batch
#define TB   8          // frames per block
#define NT   192        // threads per block (E = 384 = 2*NT)

// Scratch (allocation-free rule: __device__ globals)
__device__ float g_c[BMAX][NMAX];      // compacted token centers
__device__ float g_rsig[BMAX][NMAX];   // 1/sigma
__device__ float g_coef[BMAX][NMAX];   // 1/(sigma*sqrt(2pi))
__device__ int   g_tok[BMAX][NMAX];    // merged token ids (compacted)
__device__ float g_cumtot[BMAX];       // total duration per batch
__device__ int2  g_win[BMAX][GMAX];    // per frame-group token window [nlo, nhi]

// ---------------------------------------------------------------------------
// Kernel 1 (fused): merge pairs + shuffle-scan cumsum + compaction of
// zero-weight tokens (pad or zero-duration contribute EXACTLY 0 weight:
// sigma=1e-6 gives |z|>=5e5 so expf underflows to 0 in fp32, matching the
// reference's own underflow) + per-group window binary search in shared mem.
// One block per batch, 1024 threads.
// ---------------------------------------------------------------------------
__global__ void __launch_bounds__(1024)
prep_kernel(const int* __restrict__ text,
            const int* __restrict__ durs,
            int L, int N, int G) {
    const int b    = blockIdx.x;
    const int tid  = threadIdx.x;
    const int wrp  = tid >> 5;
    const int lane = tid & 31;

    float dm = 0.f;
    int   tk = 0;
    if (tid < N) {
        if (tid == 0) {
            dm = (float)durs[b * L];
            tk = text[b * L];
        } else {
            dm = (float)(durs[b * L + 2 * tid - 1] + durs[b * L + 2 * tid]);
            tk = text[b * L + 2 * tid - 1];
        }
    }
    const int keep = (tid < N && tk != 0 && dm > 0.f) ? 1 : 0;

    // ---- two-level inclusive scan over (dm, keep) via shuffles ----
    __shared__ float s_wd[32];
    __shared__ int   s_wk[32];
    float cum = dm;
    int   pos = keep;
    #pragma unroll
    for (int off = 1; off < 32; off <<= 1) {
        float fv = __shfl_up_sync(0xffffffffu, cum, off);
        int   iv = __shfl_up_sync(0xffffffffu, pos, off);
        if (lane >= off) { cum += fv; pos += iv; }
    }
    if (lane == 31) { s_wd[wrp] = cum; s_wk[wrp] = pos; }
    __syncthreads();
    if (wrp == 0) {
        float fv = s_wd[lane];
        int   iv = s_wk[lane];
        #pragma unroll
        for (int off = 1; off < 32; off <<= 1) {
            float f2 = __shfl_up_sync(0xffffffffu, fv, off);
            int   i2 = __shfl_up_sync(0xffffffffu, iv, off);
            if (lane >= off) { fv += f2; iv += i2; }
        }
        s_wd[lane] = fv; s_wk[lane] = iv;
    }
    __syncthreads();
    if (wrp > 0) { cum += s_wd[wrp - 1]; pos += s_wk[wrp - 1]; }

    // ---- emit compacted token params ----
    __shared__ float s_c[NMAX];
    __shared__ int   s_n2;
    if (keep) {
        const int   o   = pos - 1;
        const float sig = dm * 0.5f + 1e-6f;     // d / SIGMA_C + EPS, SIGMA_C = 2
        const float c   = cum - 0.5f * dm;
        g_c[b][o]    = c;
        g_rsig[b][o] = 1.0f / sig;
        g_coef[b][o] = 0.3989422804014327f / sig;
        g_tok[b][o]  = tk;
        s_c[o]       = c;
    }
    if (tid == N - 1) { g_cumtot[b] = cum; s_n2 = pos; }
    __syncthreads();

    // ---- per frame-group windows via binary search in shared centers ----
    // Window |t-c| <= 18: truncated tokens contribute <= ~1e-7 relative
    // (every valid frame has a contributor within ~6 frames, w >= 0.018).
    if (tid < G) {
        const int   N2  = s_n2;
        const float t0f = (float)(tid * TB);
        const float tlo = t0f + 0.5f - 18.f;
        const float thi = t0f + ((float)TB - 0.5f) + 18.f;
        int lo = 0, hi = N2;
        while (lo < hi) { int m = (lo + hi) >> 1; if (s_c[m] < tlo) lo = m + 1; else hi = m; }
        const int nlo = lo;
        hi = N2;
        while (lo < hi) { int m = (lo + hi) >> 1; if (s_c[m] <= thi) lo = m + 1; else hi = m; }
        g_win[b][tid] = make_int2(nlo, lo - 1);
    }
}

// ---------------------------------------------------------------------------
// Kernel 2: one block per (b, 8 frames). 192 threads; thread owns ONE float2
// of the embedding dim (E = 384 = 192*2) -> 16 accumulator floats, low regs,
// high occupancy. After compaction token centers are spaced >= 1 frame, so
// the 43-frame window holds <= 44 tokens < 192: SINGLE staging chunk.
// Hot loop per token: 1 LDG.64 + 2 broadcast LDS.128 + 16 FFMA.
// Per-frame weight sums reduced by warp 0 after the loop; epilogue scales.
// ---------------------------------------------------------------------------
__global__ void __launch_bounds__(NT)
lenreg_kernel(const float* __restrict__ emb,
              float* __restrict__ out,
              int T) {
    const int b   = blockIdx.y;
    const int t0  = blockIdx.x * TB;
    const int tid = threadIdx.x;

    float2* obase2 = (float2*)(out + ((size_t)b * T + t0) * 384) + tid;
    const float cumtot = g_cumtot[b];

    // Entire block beyond sample duration -> zeros and exit (~25% of blocks)
    if ((float)t0 + 0.5f >= cumtot) {
        const float2 z = make_float2(0.f, 0.f);
        #pragma unroll
        for (int tt = 0; tt < TB; tt++) obase2[tt * NT] = z;
        return;
    }

    const int2  win = g_win[b][blockIdx.x];
    const int   nlo = win.x;
    const int   cnt = min(win.y - win.x + 1, NT);   // guaranteed <= 44
    const float t0f = (float)t0;

    __shared__ float4 Wt4[128 * 2];    // [token][frame/4] raw weights (8 frames)
    __shared__ int    off_s[128];      // byte offsets into emb table
    __shared__ float  s_inv[TB];

    // ---- stage raw weights for own token (single chunk) ----
    if (tid < cnt) {
        const int   n  = nlo + tid;
        const float c  = g_c[b][n];
        const float rs = g_rsig[b][n];
        const float cf = g_coef[b][n];
        float w[TB];
        #pragma unroll
        for (int tt = 0; tt < TB; tt++) {
            float z = (t0f + (float)tt + 0.5f - c) * rs;
            w[tt] = cf * __expf(-0.5f * z * z);
        }
        Wt4[tid * 2 + 0] = make_float4(w[0], w[1], w[2], w[3]);
        Wt4[tid * 2 + 1] = make_float4(w[4], w[5], w[6], w[7]);
        off_s[tid] = g_tok[b][n] * 1536;   // *384 floats *4 bytes
    }
    __syncthreads();

    float2 acc[TB];
    #pragma unroll
    for (int tt = 0; tt < TB; tt++) acc[tt] = make_float2(0.f, 0.f);

    // ---- accumulate: 1 LDG.64 + 2 LDS.128 + 16 FFMA per token ----
    #pragma unroll 2
    for (int j = 0; j < cnt; j++) {
        const float2 e = *(const float2*)((const char*)emb + off_s[j] + (tid << 3));
        const float4 w0 = Wt4[j * 2 + 0];
        const float4 w1 = Wt4[j * 2 + 1];
        acc[0].x += w0.x * e.x; acc[0].y += w0.x * e.y;
        acc[1].x += w0.y * e.x; acc[1].y += w0.y * e.y;
        acc[2].x += w0.z * e.x; acc[2].y += w0.z * e.y;
        acc[3].x += w0.w * e.x; acc[3].y += w0.w * e.y;
        acc[4].x += w1.x * e.x; acc[4].y += w1.x * e.y;
        acc[5].x += w1.y * e.x; acc[5].y += w1.y * e.y;
        acc[6].x += w1.z * e.x; acc[6].y += w1.z * e.y;
        acc[7].x += w1.w * e.x; acc[7].y += w1.w * e.y;
    }

    // ---- per-frame weight sums: warp 0, lane = (token-phase, frame) ----
    if (tid < 32) {
        const int f  = tid & 7;          // frame
        const int j0 = tid >> 3;         // token phase 0..3
        const float* Wtf = (const float*)Wt4;
        float s = 0.f;
        for (int j = j0; j < cnt; j += 4) s += Wtf[j * TB + f];
        s += __shfl_xor_sync(0xffffffffu, s, 8);
        s += __shfl_xor_sync(0xffffffffu, s, 16);
        if (tid < TB) {
            const bool valid = (t0f + (float)tid + 0.5f) < cumtot;
            s_inv[tid] = valid ? 1.0f / (s + 1e-6f) : 0.f;
        }
    }
    __syncthreads();

    // ---- deferred normalization + 8 STG.64 ----
    #pragma unroll
    for (int tt = 0; tt < TB; tt++) {
        const float inv = s_inv[tt];
        float2 r = acc[tt];
        r.x *= inv; r.y *= inv;
        obase2[tt * NT] = r;
    }
}

// ---------------------------------------------------------------------------
extern "C" void kernel_launch(void* const* d_in, const int* in_sizes, int n_in,
                              void* d_out, int out_size) {
    const int*   text = (const int*)d_in[0];
    const int*   durs = (const int*)d_in[1];
    const float* emb  = (const float*)d_in[2];
    float* out = (float*)d_out;

    const int B = 32;
    const int L = in_sizes[0] / B;        // 1025
    const int N = (L + 1) / 2;            // 513
    const int T = out_size / (B * 384);   // 2048
    const int G = T / TB;                 // 256 frame-groups per batch

    prep_kernel<<<B, 1024>>>(text, durs, L, N, G);

    dim3 grid(G, B);
    lenreg_kernel<<<grid, NT>>>(emb, out, T);
}

// round 16
// speedup vs baseline: 1.0838x; 1.0838x over previous
#include <cuda_runtime.h>
#include <cuda_bf16.h>

#define BMAX 32
#define NMAX 640
#define GMAX 512        // max frame-groups per batch
#define TB   8          // frames per block
#define NT   96         // threads per block (E = 384 = 4*NT)

// Scratch (allocation-free rule: __device__ globals)
__device__ float g_c[BMAX][NMAX];      // compacted token centers
__device__ float g_rsig[BMAX][NMAX];   // 1/sigma
__device__ float g_coef[BMAX][NMAX];   // 1/(sigma*sqrt(2pi))
__device__ int   g_tok[BMAX][NMAX];    // merged token ids (compacted)
__device__ float g_cumtot[BMAX];       // total duration per batch
__device__ int2  g_win[BMAX][GMAX];    // per frame-group token window [nlo, nhi]

// ---------------------------------------------------------------------------
// Kernel 1 (fused): merge pairs + shuffle-scan cumsum + compaction of
// zero-weight tokens (pad or zero-duration contribute EXACTLY 0 weight:
// sigma=1e-6 gives |z|>=5e5 so expf underflows to 0 in fp32, matching the
// reference's own underflow) + per-group window binary search in shared mem.
// One block per batch, 1024 threads.
// ---------------------------------------------------------------------------
__global__ void __launch_bounds__(1024)
prep_kernel(const int* __restrict__ text,
            const int* __restrict__ durs,
            int L, int N, int G) {
    const int b    = blockIdx.x;
    const int tid  = threadIdx.x;
    const int wrp  = tid >> 5;
    const int lane = tid & 31;

    float dm = 0.f;
    int   tk = 0;
    if (tid < N) {
        if (tid == 0) {
            dm = (float)durs[b * L];
            tk = text[b * L];
        } else {
            dm = (float)(durs[b * L + 2 * tid - 1] + durs[b * L + 2 * tid]);
            tk = text[b * L + 2 * tid - 1];
        }
    }
    const int keep = (tid < N && tk != 0 && dm > 0.f) ? 1 : 0;

    // ---- two-level inclusive scan over (dm, keep) via shuffles ----
    __shared__ float s_wd[32];
    __shared__ int   s_wk[32];
    float cum = dm;
    int   pos = keep;
    #pragma unroll
    for (int off = 1; off < 32; off <<= 1) {
        float fv = __shfl_up_sync(0xffffffffu, cum, off);
        int   iv = __shfl_up_sync(0xffffffffu, pos, off);
        if (lane >= off) { cum += fv; pos += iv; }
    }
    if (lane == 31) { s_wd[wrp] = cum; s_wk[wrp] = pos; }
    __syncthreads();
    if (wrp == 0) {
        float fv = s_wd[lane];
        int   iv = s_wk[lane];
        #pragma unroll
        for (int off = 1; off < 32; off <<= 1) {
            float f2 = __shfl_up_sync(0xffffffffu, fv, off);
            int   i2 = __shfl_up_sync(0xffffffffu, iv, off);
            if (lane >= off) { fv += f2; iv += i2; }
        }
        s_wd[lane] = fv; s_wk[lane] = iv;
    }
    __syncthreads();
    if (wrp > 0) { cum += s_wd[wrp - 1]; pos += s_wk[wrp - 1]; }

    // ---- emit compacted token params ----
    __shared__ float s_c[NMAX];
    __shared__ int   s_n2;
    if (keep) {
        const int   o   = pos - 1;
        const float sig = dm * 0.5f + 1e-6f;     // d / SIGMA_C + EPS, SIGMA_C = 2
        const float c   = cum - 0.5f * dm;
        g_c[b][o]    = c;
        g_rsig[b][o] = 1.0f / sig;
        g_coef[b][o] = 0.3989422804014327f / sig;
        g_tok[b][o]  = tk;
        s_c[o]       = c;
    }
    if (tid == N - 1) { g_cumtot[b] = cum; s_n2 = pos; }
    __syncthreads();

    // ---- per frame-group windows via binary search in shared centers ----
    // Window |t-c| <= 18: truncated tokens contribute <= ~1e-7 relative
    // (every valid frame has a contributor within ~6 frames, w >= 0.018).
    if (tid < G) {
        const int   N2  = s_n2;
        const float t0f = (float)(tid * TB);
        const float tlo = t0f + 0.5f - 18.f;
        const float thi = t0f + ((float)TB - 0.5f) + 18.f;
        int lo = 0, hi = N2;
        while (lo < hi) { int m = (lo + hi) >> 1; if (s_c[m] < tlo) lo = m + 1; else hi = m; }
        const int nlo = lo;
        hi = N2;
        while (lo < hi) { int m = (lo + hi) >> 1; if (s_c[m] <= thi) lo = m + 1; else hi = m; }
        g_win[b][tid] = make_int2(nlo, lo - 1);
    }
}

// 32 FMAs of one token's weights (w0,w1) against one embedding float4 (e)
__device__ __forceinline__ void accum_token(float4 (&acc)[TB],
                                            const float4 w0, const float4 w1,
                                            const float4 e) {
    acc[0].x += w0.x * e.x; acc[0].y += w0.x * e.y; acc[0].z += w0.x * e.z; acc[0].w += w0.x * e.w;
    acc[1].x += w0.y * e.x; acc[1].y += w0.y * e.y; acc[1].z += w0.y * e.z; acc[1].w += w0.y * e.w;
    acc[2].x += w0.z * e.x; acc[2].y += w0.z * e.y; acc[2].z += w0.z * e.z; acc[2].w += w0.z * e.w;
    acc[3].x += w0.w * e.x; acc[3].y += w0.w * e.y; acc[3].z += w0.w * e.z; acc[3].w += w0.w * e.w;
    acc[4].x += w1.x * e.x; acc[4].y += w1.x * e.y; acc[4].z += w1.x * e.z; acc[4].w += w1.x * e.w;
    acc[5].x += w1.y * e.x; acc[5].y += w1.y * e.y; acc[5].z += w1.y * e.z; acc[5].w += w1.y * e.w;
    acc[6].x += w1.z * e.x; acc[6].y += w1.z * e.y; acc[6].z += w1.z * e.z; acc[6].w += w1.z * e.w;
    acc[7].x += w1.w * e.x; acc[7].y += w1.w * e.y; acc[7].z += w1.w * e.z; acc[7].w += w1.w * e.w;
}

// ---------------------------------------------------------------------------
// Kernel 2: one block per (b, 8 frames). 96 threads; thread owns ONE float4
// of the embedding dim (E = 384 = 96*4). The j-loop processes tokens in
// batches of 4: four independent LDG.128 issued back-to-back (MLP=4) before
// the FMA bursts, halving the exposed L2 latency vs unroll-2. Per-frame
// weight sums reduced from shared after the loop; epilogue scales + STG.128.
// ---------------------------------------------------------------------------
__global__ void __launch_bounds__(NT)
lenreg_kernel(const float* __restrict__ emb,
              float* __restrict__ out,
              int T) {
    const int b   = blockIdx.y;
    const int t0  = blockIdx.x * TB;
    const int tid = threadIdx.x;

    float4* obase4 = (float4*)(out + ((size_t)b * T + t0) * 384) + tid;
    const float cumtot = g_cumtot[b];

    // Entire block beyond sample duration -> zeros and exit (~25% of blocks)
    if ((float)t0 + 0.5f >= cumtot) {
        const float4 z = make_float4(0.f, 0.f, 0.f, 0.f);
        #pragma unroll
        for (int tt = 0; tt < TB; tt++) obase4[tt * NT] = z;
        return;
    }

    const float* __restrict__ cb    = g_c[b];
    const float* __restrict__ rsigb = g_rsig[b];
    const float* __restrict__ coefb = g_coef[b];
    const int*   __restrict__ tokb  = g_tok[b];

    const int2  win = g_win[b][blockIdx.x];
    const int   nlo = win.x;
    const int   nhi = win.y;
    const float t0f = (float)t0;

    __shared__ float4 Wt4[NT * 2];     // [token][frame/4] raw weights (8 frames)
    __shared__ int    off_s[NT];       // byte offsets into emb table
    __shared__ float  s_inv[TB];

    float4 acc[TB];
    #pragma unroll
    for (int tt = 0; tt < TB; tt++) acc[tt] = make_float4(0.f, 0.f, 0.f, 0.f);
    float ssum = 0.f;                  // running frame sum (threads 0..7 only)

    for (int base = nlo; base <= nhi; base += NT) {
        const int n = base + tid;
        // ---- stage raw weights for own token (compacted window, runs once) --
        if (n <= nhi) {
            const float c  = cb[n];
            const float rs = rsigb[n];
            const float cf = coefb[n];
            float w[TB];
            #pragma unroll
            for (int tt = 0; tt < TB; tt++) {
                float z = (t0f + (float)tt + 0.5f - c) * rs;
                w[tt] = cf * __expf(-0.5f * z * z);
            }
            Wt4[tid * 2 + 0] = make_float4(w[0], w[1], w[2], w[3]);
            Wt4[tid * 2 + 1] = make_float4(w[4], w[5], w[6], w[7]);
            off_s[tid] = tokb[n] * 1536;   // *384 floats *4 bytes
        }
        __syncthreads();

        const int cnt = min(NT, nhi - base + 1);
        const char* __restrict__ ebase = (const char*)emb;
        const int   eoff = tid << 4;

        // ---- accumulate, 4 tokens per batch: MLP=4 on the gather ----
        int j = 0;
        for (; j + 4 <= cnt; j += 4) {
            const float4 e0 = *(const float4*)(ebase + off_s[j + 0] + eoff);
            const float4 e1 = *(const float4*)(ebase + off_s[j + 1] + eoff);
            const float4 e2 = *(const float4*)(ebase + off_s[j + 2] + eoff);
            const float4 e3 = *(const float4*)(ebase + off_s[j + 3] + eoff);
            accum_token(acc, Wt4[(j + 0) * 2], Wt4[(j + 0) * 2 + 1], e0);
            accum_token(acc, Wt4[(j + 1) * 2], Wt4[(j + 1) * 2 + 1], e1);
            accum_token(acc, Wt4[(j + 2) * 2], Wt4[(j + 2) * 2 + 1], e2);
            accum_token(acc, Wt4[(j + 3) * 2], Wt4[(j + 3) * 2 + 1], e3);
        }
        for (; j < cnt; j++) {
            const float4 e = *(const float4*)(ebase + off_s[j] + eoff);
            accum_token(acc, Wt4[j * 2], Wt4[j * 2 + 1], e);
        }

        // ---- per-frame weight sums from the (still resident) staged weights;
        //      thread tt (0..7) owns frame tt, so no cross-thread hazard ----
        if (tid < TB) {
            const float* Wtf = (const float*)Wt4;
            float s = 0.f;
            for (int jj = 0; jj < cnt; jj++) s += Wtf[jj * TB + tid];
            ssum += s;
        }
        __syncthreads();   // reduce + loop reads done before Wt reuse / epilogue
    }

    // ---- deferred normalization + 8 STG.128 ----
    if (tid < TB) {
        const bool valid = (t0f + (float)tid + 0.5f) < cumtot;
        s_inv[tid] = valid ? 1.0f / (ssum + 1e-6f) : 0.f;
    }
    __syncthreads();

    #pragma unroll
    for (int tt = 0; tt < TB; tt++) {
        const float inv = s_inv[tt];
        float4 r = acc[tt];
        r.x *= inv; r.y *= inv; r.z *= inv; r.w *= inv;
        obase4[tt * NT] = r;
    }
}

// ---------------------------------------------------------------------------
extern "C" void kernel_launch(void* const* d_in, const int* in_sizes, int n_in,
                              void* d_out, int out_size) {
    const int*   text = (const int*)d_in[0];
    const int*   durs = (const int*)d_in[1];
    const float* emb  = (const float*)d_in[2];
    float* out = (float*)d_out;

    const int B = 32;
    const int L = in_sizes[0] / B;        // 1025
    const int N = (L + 1) / 2;            // 513
    const int T = out_size / (B * 384);   // 2048
    const int G = T / TB;                 // 256 frame-groups per batch

    prep_kernel<<<B, 1024>>>(text, durs, L, N, G);

    dim3 grid(G, B);
    lenreg_kernel<<<grid, NT>>>(emb, out, T);
}